// round 1
// baseline (speedup 1.0000x reference)
#include <cuda_runtime.h>

// Problem constants (fixed by the dataset)
#define RDIM 256
#define CDIM 32
#define BPL 12                 // B*3 planes
#define NPTS 524288            // B*N = 4*131072
#define THREADS 256
#define NTILES (NPTS / THREADS)

typedef unsigned long long ull;

// Transposed triplanes scratch: [bp][y][x][c], fp32. ~100.7 MB device global.
__device__ float g_tp[(size_t)BPL * RDIM * RDIM * CDIM];

// ---------- packed f32x2 helpers ----------
__device__ __forceinline__ ull f2fma(ull a, ull b, ull c) {
    ull d;
    asm("fma.rn.f32x2 %0, %1, %2, %3;" : "=l"(d) : "l"(a), "l"(b), "l"(c));
    return d;
}
__device__ __forceinline__ ull f2add(ull a, ull b) {
    ull d;
    asm("add.rn.f32x2 %0, %1, %2;" : "=l"(d) : "l"(a), "l"(b));
    return d;
}
__device__ __forceinline__ ull f2pack(float lo, float hi) {
    ull d;
    asm("mov.b64 %0, {%1, %2};" : "=l"(d) : "f"(lo), "f"(hi));
    return d;
}
__device__ __forceinline__ void f2unpack(ull v, float& lo, float& hi) {
    asm("mov.b64 {%0, %1}, %2;" : "=f"(lo), "=f"(hi) : "l"(v));
}

// ---------- Kernel 1: transpose [bp][c][y][x] -> [bp][y][x][c] ----------
__global__ void transpose_planes(const float* __restrict__ in) {
    __shared__ float t[32][33];
    int tx = threadIdx.x;          // 0..31
    int ty = threadIdx.y;          // 0..7
    int xb = blockIdx.x * 32;      // x tile base
    int y  = blockIdx.y;           // 0..255
    int bp = blockIdx.z;           // 0..11

    const float* src = in + ((size_t)bp * CDIM) * (RDIM * RDIM) + (size_t)y * RDIM + xb;
#pragma unroll
    for (int i = 0; i < 4; i++) {
        int c = ty + i * 8;
        t[c][tx] = src[(size_t)c * (RDIM * RDIM) + tx];
    }
    __syncthreads();
    float* dst = g_tp + (((size_t)bp * RDIM + y) * RDIM + xb) * CDIM;
#pragma unroll
    for (int i = 0; i < 4; i++) {
        int xl = ty + i * 8;
        dst[(size_t)xl * CDIM + tx] = t[tx][xl];
    }
}

// ---------- Kernel 2: fused sample + product + MLP ----------
// smem layout (floats):
//   sw1t : 16384  (w1 transposed: [h][g], g-pairs contiguous for LDS.64)
//   sw0  : 4096   (w0 natural:   [j][c], c-pairs contiguous)
//   sh0  : 32768  (per-thread h0: [j][tid])
//   sb0  : 128, sb1 : 128, sw2 : 128
#define SMEM_FLOATS (16384 + 4096 + 32768 + 128 + 128 + 128)

__global__ __launch_bounds__(THREADS, 1)
void fused_triplane_mlp(const float* __restrict__ coords,
                        const float* __restrict__ w0, const float* __restrict__ b0,
                        const float* __restrict__ w1, const float* __restrict__ b1,
                        const float* __restrict__ w2, const float* __restrict__ b2,
                        float* __restrict__ out) {
    extern __shared__ float sm[];
    float* sw1t = sm;
    float* sw0  = sm + 16384;
    float* sh0  = sm + 20480;
    float* sb0  = sm + 53248;
    float* sb1  = sm + 53376;
    float* sw2  = sm + 53504;

    const int tid = threadIdx.x;

    // Stage weights once per (persistent) CTA.
    for (int i = tid; i < 16384; i += THREADS)
        sw1t[i] = w1[((i & 127) << 7) | (i >> 7)];   // sw1t[h*128+g] = w1[g*128+h]
    for (int i = tid; i < 4096; i += THREADS)
        sw0[i] = w0[i];
    if (tid < 128) { sb0[tid] = b0[tid]; sb1[tid] = b1[tid]; sw2[tid] = w2[tid]; }
    const float bias2 = b2[0];
    __syncthreads();

    for (int tile = blockIdx.x; tile < NTILES; tile += gridDim.x) {
        const int p = tile * THREADS + tid;
        const float cx = coords[3 * p + 0];
        const float cy = coords[3 * p + 1];
        const float cz = coords[3 * p + 2];
        const int b = p >> 17;   // 131072 pts per batch

        // ---- trilinear-of-3-planes gather: f[c] = prod over planes ----
        float f[CDIM];
#pragma unroll
        for (int pl = 0; pl < 3; pl++) {
            // plane0:(x,y)  plane1:(y,z)  plane2:(x,z); first coord -> W, second -> H
            const float u = (pl == 1) ? cy : cx;
            const float v = (pl == 0) ? cy : cz;
            const float xf = (u + 1.0f) * 127.5f;
            const float yf = (v + 1.0f) * 127.5f;
            const float x0f = floorf(xf), y0f = floorf(yf);
            const float wx = xf - x0f, wy = yf - y0f;
            const int ix0 = (int)x0f, iy0 = (int)y0f;
            const int ix1 = ix0 + 1,  iy1 = iy0 + 1;
            const float mx0 = (ix0 >= 0 && ix0 < RDIM) ? 1.0f : 0.0f;
            const float mx1 = (ix1 >= 0 && ix1 < RDIM) ? 1.0f : 0.0f;
            const float my0 = (iy0 >= 0 && iy0 < RDIM) ? 1.0f : 0.0f;
            const float my1 = (iy1 >= 0 && iy1 < RDIM) ? 1.0f : 0.0f;
            const int ix0c = min(max(ix0, 0), RDIM - 1);
            const int ix1c = min(max(ix1, 0), RDIM - 1);
            const int iy0c = min(max(iy0, 0), RDIM - 1);
            const int iy1c = min(max(iy1, 0), RDIM - 1);

            const float w00 = (1.0f - wx) * (1.0f - wy) * mx0 * my0;
            const float w01 = wx * (1.0f - wy) * mx1 * my0;
            const float w10 = (1.0f - wx) * wy * mx0 * my1;
            const float w11 = wx * wy * mx1 * my1;

            const float4* base =
                (const float4*)(g_tp + ((size_t)(b * 3 + pl) * RDIM * RDIM) * CDIM);
            const float4* p00 = base + (size_t)(iy0c * RDIM + ix0c) * 8;
            const float4* p01 = base + (size_t)(iy0c * RDIM + ix1c) * 8;
            const float4* p10 = base + (size_t)(iy1c * RDIM + ix0c) * 8;
            const float4* p11 = base + (size_t)(iy1c * RDIM + ix1c) * 8;
#pragma unroll
            for (int k = 0; k < 8; k++) {
                const float4 a = p00[k], bb = p01[k], cc = p10[k], dd = p11[k];
                float s0 = w00 * a.x + w01 * bb.x + w10 * cc.x + w11 * dd.x;
                float s1 = w00 * a.y + w01 * bb.y + w10 * cc.y + w11 * dd.y;
                float s2 = w00 * a.z + w01 * bb.z + w10 * cc.z + w11 * dd.z;
                float s3 = w00 * a.w + w01 * bb.w + w10 * cc.w + w11 * dd.w;
                if (pl == 0) {
                    f[4 * k + 0] = s0; f[4 * k + 1] = s1;
                    f[4 * k + 2] = s2; f[4 * k + 3] = s3;
                } else {
                    f[4 * k + 0] *= s0; f[4 * k + 1] *= s1;
                    f[4 * k + 2] *= s2; f[4 * k + 3] *= s3;
                }
            }
        }

        // pack feature pairs (reduction over c)
        ull fp[16];
#pragma unroll
        for (int i = 0; i < 16; i++) fp[i] = f2pack(f[2 * i], f[2 * i + 1]);

        // ---- layer 0: h0[j] = relu(b0[j] + sum_c w0[j,c] f[c]) -> smem ----
        for (int j = 0; j < 128; j++) {
            ull acc[4] = {0ull, 0ull, 0ull, 0ull};
            const ull* wrow = (const ull*)(sw0 + j * 32);
#pragma unroll
            for (int q = 0; q < 16; q++)
                acc[q & 3] = f2fma(wrow[q], fp[q], acc[q & 3]);
            ull s = f2add(f2add(acc[0], acc[1]), f2add(acc[2], acc[3]));
            float lo, hi; f2unpack(s, lo, hi);
            float h = lo + hi + sb0[j];
            sh0[(j << 8) + tid] = fmaxf(h, 0.0f);
        }

        // ---- layer 1: h1 pairs (packed over g) accumulated over h ----
        ull hp[64];
#pragma unroll
        for (int q = 0; q < 64; q++) hp[q] = 0ull;
        for (int h = 0; h < 128; h++) {
            const float hv = sh0[(h << 8) + tid];
            const ull hh = f2pack(hv, hv);
            const ull* wrow = (const ull*)(sw1t + (h << 7));
#pragma unroll
            for (int q = 0; q < 64; q++)
                hp[q] = f2fma(wrow[q], hh, hp[q]);
        }

        // ---- layer 2: out = b2 + sum_g w2[g] * relu(h1[g] + b1[g]) ----
        float acc = bias2;
#pragma unroll
        for (int q = 0; q < 64; q++) {
            float v0, v1; f2unpack(hp[q], v0, v1);
            v0 = fmaxf(v0 + sb1[2 * q], 0.0f);
            v1 = fmaxf(v1 + sb1[2 * q + 1], 0.0f);
            acc = fmaf(sw2[2 * q], v0, acc);
            acc = fmaf(sw2[2 * q + 1], v1, acc);
        }
        out[p] = acc;
    }
}

// ---------- host ----------
extern "C" void kernel_launch(void* const* d_in, const int* in_sizes, int n_in,
                              void* d_out, int out_size) {
    const float* triplanes = (const float*)d_in[0];
    const float* coords    = (const float*)d_in[1];
    const float* w0 = (const float*)d_in[2];
    const float* b0 = (const float*)d_in[3];
    const float* w1 = (const float*)d_in[4];
    const float* b1 = (const float*)d_in[5];
    const float* w2 = (const float*)d_in[6];
    const float* b2 = (const float*)d_in[7];
    float* out = (float*)d_out;

    // 1) transpose planes into channel-contiguous scratch
    dim3 tgrid(RDIM / 32, RDIM, BPL);
    dim3 tblk(32, 8);
    transpose_planes<<<tgrid, tblk>>>(triplanes);

    // 2) fused sample + MLP (persistent grid = #SMs, opt-in large smem)
    static int sms = 0;
    if (sms == 0) {
        cudaDeviceGetAttribute(&sms, cudaDevAttrMultiProcessorCount, 0);
        cudaFuncSetAttribute(fused_triplane_mlp,
                             cudaFuncAttributeMaxDynamicSharedMemorySize,
                             SMEM_FLOATS * (int)sizeof(float));
    }
    fused_triplane_mlp<<<sms, THREADS, SMEM_FLOATS * sizeof(float)>>>(
        coords, w0, b0, w1, b1, w2, b2, out);
}

// round 3
// speedup vs baseline: 3.6940x; 3.6940x over previous
#include <cuda_runtime.h>
#include <cuda_bf16.h>
#include <cstdint>

#define RDIM 256
#define CDIM 32
#define NPTS 524288
#define THREADS 256
#define NWTILES (NPTS / 16)        // 32768 warp-tiles of 16 points

// Transposed triplanes scratch: [bp][y][x][c], fp32 (~100.7 MB)
__device__ float g_tp[(size_t)12 * RDIM * RDIM * CDIM];

// ---------------- smem layout (bytes) ----------------
// padded row strides chosen so ldmatrix's 8 row-addresses land in 8 distinct
// 16B bank groups: 80 = 5*16 (mod 128 cycle covers all), 272 = 17*16.
#define OFF_W1HI 0                  // 128 rows * 272B
#define OFF_W1LO 34816
#define OFF_W0HI 69632              // 128 rows * 80B
#define OFF_W0LO 79872
#define OFF_FHI  90112              // 128 rows * 80B (16 rows per warp)
#define OFF_FLO  100352
#define OFF_B0   110592             // 128 f32
#define OFF_B1   111104
#define OFF_W2   111616
#define SMEM_BYTES 112640

// ---------------- mma / ldmatrix helpers ----------------
__device__ __forceinline__ uint32_t smem_u32(const void* p) {
    uint32_t a;
    asm("{ .reg .u64 t; cvta.to.shared.u64 t, %1; cvt.u32.u64 %0, t; }" : "=r"(a) : "l"(p));
    return a;
}
__device__ __forceinline__ void mma16816(float* d, const uint32_t* a, const uint32_t* b) {
    asm volatile("mma.sync.aligned.m16n8k16.row.col.f32.bf16.bf16.f32 "
                 "{%0,%1,%2,%3}, {%4,%5,%6,%7}, {%8,%9}, {%0,%1,%2,%3};"
                 : "+f"(d[0]), "+f"(d[1]), "+f"(d[2]), "+f"(d[3])
                 : "r"(a[0]), "r"(a[1]), "r"(a[2]), "r"(a[3]), "r"(b[0]), "r"(b[1]));
}
__device__ __forceinline__ void ldsm4(uint32_t* r, uint32_t addr) {
    asm volatile("ldmatrix.sync.aligned.m8n8.x4.shared.b16 {%0,%1,%2,%3}, [%4];"
                 : "=r"(r[0]), "=r"(r[1]), "=r"(r[2]), "=r"(r[3]) : "r"(addr));
}
// pack (lo=v0, hi=v1) to bf16x2; also produce residual pack
__device__ __forceinline__ void split2(float v0, float v1, uint32_t& hi, uint32_t& lo) {
    asm("cvt.rn.bf16x2.f32 %0, %1, %2;" : "=r"(hi) : "f"(v1), "f"(v0));
    float f0 = __uint_as_float(hi << 16);
    float f1 = __uint_as_float(hi & 0xFFFF0000u);
    float r0 = v0 - f0, r1 = v1 - f1;
    asm("cvt.rn.bf16x2.f32 %0, %1, %2;" : "=r"(lo) : "f"(r1), "f"(r0));
}

// ---------- Kernel 1: transpose [bp][c][y][x] -> [bp][y][x][c] ----------
__global__ void transpose_planes(const float* __restrict__ in) {
    __shared__ float t[32][33];
    int tx = threadIdx.x, ty = threadIdx.y;
    int xb = blockIdx.x * 32, y = blockIdx.y, bp = blockIdx.z;
    const float* src = in + ((size_t)bp * CDIM) * (RDIM * RDIM) + (size_t)y * RDIM + xb;
#pragma unroll
    for (int i = 0; i < 4; i++) {
        int c = ty + i * 8;
        t[c][tx] = src[(size_t)c * (RDIM * RDIM) + tx];
    }
    __syncthreads();
    float* dst = g_tp + (((size_t)bp * RDIM + y) * RDIM + xb) * CDIM;
#pragma unroll
    for (int i = 0; i < 4; i++) {
        int xl = ty + i * 8;
        dst[(size_t)xl * CDIM + tx] = t[tx][xl];
    }
}

// ---------- Kernel 2: gather + bf16 mma.sync MLP ----------
__global__ __launch_bounds__(THREADS, 1)
void fused_triplane_mlp_mma(const float* __restrict__ coords,
                            const float* __restrict__ w0, const float* __restrict__ b0,
                            const float* __restrict__ w1, const float* __restrict__ b1,
                            const float* __restrict__ w2, const float* __restrict__ b2,
                            float* __restrict__ out) {
    extern __shared__ char sm[];
    const uint32_t sb = smem_u32(sm);
    const int tid = threadIdx.x;
    const int wid = tid >> 5;
    const int lane = tid & 31;

    float* sB0 = (float*)(sm + OFF_B0);
    float* sB1 = (float*)(sm + OFF_B1);
    float* sW2 = (float*)(sm + OFF_W2);

    // ---- stage weights: bf16 hi/lo split into padded layouts ----
    for (int i = tid; i < 16384; i += THREADS) {     // w1[g][h], stride 272B
        int g = i >> 7, h = i & 127;
        float v = w1[i];
        __nv_bfloat16 hb = __float2bfloat16(v);
        float res = v - __bfloat162float(hb);
        *(unsigned short*)(sm + OFF_W1HI + g * 272 + h * 2) = *(unsigned short*)&hb;
        __nv_bfloat16 lb = __float2bfloat16(res);
        *(unsigned short*)(sm + OFF_W1LO + g * 272 + h * 2) = *(unsigned short*)&lb;
    }
    for (int i = tid; i < 4096; i += THREADS) {      // w0[j][c], stride 80B
        int j = i >> 5, c = i & 31;
        float v = w0[i];
        __nv_bfloat16 hb = __float2bfloat16(v);
        float res = v - __bfloat162float(hb);
        *(unsigned short*)(sm + OFF_W0HI + j * 80 + c * 2) = *(unsigned short*)&hb;
        __nv_bfloat16 lb = __float2bfloat16(res);
        *(unsigned short*)(sm + OFF_W0LO + j * 80 + c * 2) = *(unsigned short*)&lb;
    }
    if (tid < 128) { sB0[tid] = b0[tid]; sB1[tid] = b1[tid]; sW2[tid] = w2[tid]; }
    const float bias2 = b2[0];
    __syncthreads();

    // ---- lane-fixed ldmatrix base addresses ----
    const int grp = lane >> 3;                // 0..3 (ldmatrix 8-lane groups)
    const int idx = lane & 7;
    // A (F tile): lanes 0-15 rows, 16-31 rows +16B (k 8-15)
    const uint32_t fA = (uint32_t)((wid * 16 + (lane & 15)) * 80 + (lane >> 4) * 16);
    const uint32_t aHI = sb + OFF_FHI + fA;
    const uint32_t aLO = sb + OFF_FLO + fA;
    // B (weights, [n][k] row-major, non-trans): groups: {n0-7,k0-7},{n0-7,k8-15},{n8-15,k0-7},{n8-15,k8-15}
    const uint32_t b0off = (uint32_t)(((grp >> 1) * 8 + idx) * 80 + (grp & 1) * 16);
    const uint32_t w0HI = sb + OFF_W0HI + b0off;
    const uint32_t w0LO = sb + OFF_W0LO + b0off;
    const uint32_t b1off = (uint32_t)(((grp >> 1) * 8 + idx) * 272 + (grp & 1) * 16);
    const uint32_t w1HI = sb + OFF_W1HI + b1off;
    const uint32_t w1LO = sb + OFF_W1LO + b1off;
    // F store coords for gather
    const int pt_sub = lane >> 3;             // point within group of 4
    const int q = lane & 7;                   // 4-channel chunk
    char* fhiw = sm + OFF_FHI + (size_t)q * 8;
    char* flow = sm + OFF_FLO + (size_t)q * 8;

    const int c2 = 2 * (lane & 3);            // D-fragment column offset

    const int gwarp = blockIdx.x * 8 + wid;
    const int nwarp = gridDim.x * 8;

    for (int wt = gwarp; wt < NWTILES; wt += nwarp) {
        const int pbase = wt * 16;

        // ================= gather: 16 points -> F rows (bf16 hi/lo) =================
        __syncwarp();
#pragma unroll 1
        for (int it = 0; it < 4; it++) {
            const int row = it * 4 + pt_sub;                 // 0..15 (warp-private)
            const int p = pbase + row;
            const float cx = coords[3 * p + 0];
            const float cy = coords[3 * p + 1];
            const float cz = coords[3 * p + 2];
            const int b = p >> 17;
            float4 acc;
#pragma unroll
            for (int pl = 0; pl < 3; pl++) {
                const float u = (pl == 1) ? cy : cx;
                const float v = (pl == 0) ? cy : cz;
                const float xf = (u + 1.0f) * 127.5f;
                const float yf = (v + 1.0f) * 127.5f;
                const float x0f = floorf(xf), y0f = floorf(yf);
                const float wx = xf - x0f, wy = yf - y0f;
                const int ix0 = (int)x0f, iy0 = (int)y0f;
                const int ix1 = ix0 + 1, iy1 = iy0 + 1;
                const float mx0 = (ix0 >= 0 && ix0 < RDIM) ? 1.0f : 0.0f;
                const float mx1 = (ix1 >= 0 && ix1 < RDIM) ? 1.0f : 0.0f;
                const float my0 = (iy0 >= 0 && iy0 < RDIM) ? 1.0f : 0.0f;
                const float my1 = (iy1 >= 0 && iy1 < RDIM) ? 1.0f : 0.0f;
                const int ix0c = min(max(ix0, 0), RDIM - 1);
                const int ix1c = min(max(ix1, 0), RDIM - 1);
                const int iy0c = min(max(iy0, 0), RDIM - 1);
                const int iy1c = min(max(iy1, 0), RDIM - 1);
                const float w00 = (1.0f - wx) * (1.0f - wy) * mx0 * my0;
                const float w01 = wx * (1.0f - wy) * mx1 * my0;
                const float w10 = (1.0f - wx) * wy * mx0 * my1;
                const float w11 = wx * wy * mx1 * my1;
                const float4* base =
                    (const float4*)(g_tp + ((size_t)(b * 3 + pl) * RDIM * RDIM) * CDIM);
                const float4 a0 = base[(size_t)(iy0c * RDIM + ix0c) * 8 + q];
                const float4 a1 = base[(size_t)(iy0c * RDIM + ix1c) * 8 + q];
                const float4 a2 = base[(size_t)(iy1c * RDIM + ix0c) * 8 + q];
                const float4 a3 = base[(size_t)(iy1c * RDIM + ix1c) * 8 + q];
                float4 s;
                s.x = w00 * a0.x + w01 * a1.x + w10 * a2.x + w11 * a3.x;
                s.y = w00 * a0.y + w01 * a1.y + w10 * a2.y + w11 * a3.y;
                s.z = w00 * a0.z + w01 * a1.z + w10 * a2.z + w11 * a3.z;
                s.w = w00 * a0.w + w01 * a1.w + w10 * a2.w + w11 * a3.w;
                if (pl == 0) acc = s;
                else { acc.x *= s.x; acc.y *= s.y; acc.z *= s.z; acc.w *= s.w; }
            }
            uint2 hi, lo;
            split2(acc.x, acc.y, hi.x, lo.x);
            split2(acc.z, acc.w, hi.y, lo.y);
            const int gr = wid * 16 + row;
            *(uint2*)(fhiw + gr * 80) = hi;
            *(uint2*)(flow + gr * 80) = lo;
        }
        __syncwarp();

        // ================= layer 0: D = F(16x32) x W0^T -> 16 n-tiles =================
        uint32_t A0h[2][4], A0l[2][4];
        ldsm4(A0h[0], aHI);       ldsm4(A0h[1], aHI + 32);
        ldsm4(A0l[0], aLO);       ldsm4(A0l[1], aLO + 32);

        float D[16][4];
#pragma unroll
        for (int m = 0; m < 16; m++) { D[m][0] = 0.f; D[m][1] = 0.f; D[m][2] = 0.f; D[m][3] = 0.f; }

#pragma unroll
        for (int ntp = 0; ntp < 8; ntp++) {
#pragma unroll
            for (int kf = 0; kf < 2; kf++) {
                uint32_t bh[4], bl[4];
                ldsm4(bh, w0HI + ntp * (16 * 80) + kf * 32);
                ldsm4(bl, w0LO + ntp * (16 * 80) + kf * 32);
                mma16816(D[2 * ntp],     A0h[kf], bh);
                mma16816(D[2 * ntp],     A0h[kf], bl);
                mma16816(D[2 * ntp],     A0l[kf], bh);
                mma16816(D[2 * ntp + 1], A0h[kf], bh + 2);
                mma16816(D[2 * ntp + 1], A0h[kf], bl + 2);
                mma16816(D[2 * ntp + 1], A0l[kf], bh + 2);
            }
        }

        // ===== epilogue0: relu(D + b0) -> bf16 hi/lo A-fragments (pure registers) =====
        uint32_t A1h[8][4], A1l[8][4];
#pragma unroll
        for (int m = 0; m < 16; m++) {
            const float2 bb = *(const float2*)(sB0 + 8 * m + c2);
            float v0 = fmaxf(D[m][0] + bb.x, 0.f);
            float v1 = fmaxf(D[m][1] + bb.y, 0.f);
            float v2 = fmaxf(D[m][2] + bb.x, 0.f);
            float v3 = fmaxf(D[m][3] + bb.y, 0.f);
            const int j = m >> 1, h = (m & 1) * 2;
            split2(v0, v1, A1h[j][h],     A1l[j][h]);
            split2(v2, v3, A1h[j][h + 1], A1l[j][h + 1]);
        }

        // ================= layer 1: D = A1(16x128) x W1^T =================
#pragma unroll
        for (int m = 0; m < 16; m++) { D[m][0] = 0.f; D[m][1] = 0.f; D[m][2] = 0.f; D[m][3] = 0.f; }

#pragma unroll
        for (int ntp = 0; ntp < 8; ntp++) {
#pragma unroll
            for (int kf = 0; kf < 8; kf++) {
                uint32_t bh[4], bl[4];
                ldsm4(bh, w1HI + ntp * (16 * 272) + kf * 32);
                ldsm4(bl, w1LO + ntp * (16 * 272) + kf * 32);
                mma16816(D[2 * ntp],     A1h[kf], bh);
                mma16816(D[2 * ntp],     A1h[kf], bl);
                mma16816(D[2 * ntp],     A1l[kf], bh);
                mma16816(D[2 * ntp + 1], A1h[kf], bh + 2);
                mma16816(D[2 * ntp + 1], A1h[kf], bl + 2);
                mma16816(D[2 * ntp + 1], A1l[kf], bh + 2);
            }
        }

        // ===== layer 2: out = b2 + sum_g w2[g] * relu(D + b1) =====
        float acc0 = 0.f, acc1 = 0.f;
#pragma unroll
        for (int m = 0; m < 16; m++) {
            const float2 bv = *(const float2*)(sB1 + 8 * m + c2);
            const float2 wv = *(const float2*)(sW2 + 8 * m + c2);
            acc0 = fmaf(fmaxf(D[m][0] + bv.x, 0.f), wv.x, acc0);
            acc0 = fmaf(fmaxf(D[m][1] + bv.y, 0.f), wv.y, acc0);
            acc1 = fmaf(fmaxf(D[m][2] + bv.x, 0.f), wv.x, acc1);
            acc1 = fmaf(fmaxf(D[m][3] + bv.y, 0.f), wv.y, acc1);
        }
        acc0 += __shfl_xor_sync(0xFFFFFFFFu, acc0, 1);
        acc0 += __shfl_xor_sync(0xFFFFFFFFu, acc0, 2);
        acc1 += __shfl_xor_sync(0xFFFFFFFFu, acc1, 1);
        acc1 += __shfl_xor_sync(0xFFFFFFFFu, acc1, 2);
        if ((lane & 3) == 0) {
            const int g = lane >> 2;
            out[pbase + g] = acc0 + bias2;
            out[pbase + g + 8] = acc1 + bias2;
        }
    }
}

// ---------------- host ----------------
extern "C" void kernel_launch(void* const* d_in, const int* in_sizes, int n_in,
                              void* d_out, int out_size) {
    const float* triplanes = (const float*)d_in[0];
    const float* coords    = (const float*)d_in[1];
    const float* w0 = (const float*)d_in[2];
    const float* b0 = (const float*)d_in[3];
    const float* w1 = (const float*)d_in[4];
    const float* b1 = (const float*)d_in[5];
    const float* w2 = (const float*)d_in[6];
    const float* b2 = (const float*)d_in[7];
    float* out = (float*)d_out;

    dim3 tgrid(RDIM / 32, RDIM, 12);
    dim3 tblk(32, 8);
    transpose_planes<<<tgrid, tblk>>>(triplanes);

    static int sms = 0;
    if (sms == 0) {
        cudaDeviceGetAttribute(&sms, cudaDevAttrMultiProcessorCount, 0);
        cudaFuncSetAttribute(fused_triplane_mlp_mma,
                             cudaFuncAttributeMaxDynamicSharedMemorySize, SMEM_BYTES);
    }
    fused_triplane_mlp_mma<<<sms, THREADS, SMEM_BYTES>>>(coords, w0, b0, w1, b1, w2, b2, out);
}

// round 4
// speedup vs baseline: 4.0102x; 1.0856x over previous
#include <cuda_runtime.h>
#include <cuda_bf16.h>
#include <cstdint>

#define RDIM 256
#define CDIM 32
#define NPTS 524288
#define THREADS 256
#define NWTILES (NPTS / 16)        // 32768 warp-tiles of 16 points

// Transposed triplanes scratch: [bp][y][x][c], fp32 (~100.7 MB)
__device__ float g_tp[(size_t)12 * RDIM * RDIM * CDIM];

// ---------------- smem layout (bytes) ----------------
#define OFF_W1HI 0                  // 128 rows * 272B
#define OFF_W1LO 34816
#define OFF_W0HI 69632              // 128 rows * 80B
#define OFF_W0LO 79872
#define OFF_FHI  90112              // 128 rows * 80B (16 rows per warp)
#define OFF_FLO  100352
#define OFF_B0   110592             // 128 f32
#define OFF_B1   111104
#define OFF_W2   111616
#define SMEM_BYTES 112640

// ---------------- mma / ldmatrix helpers ----------------
__device__ __forceinline__ uint32_t smem_u32(const void* p) {
    uint32_t a;
    asm("{ .reg .u64 t; cvta.to.shared.u64 t, %1; cvt.u32.u64 %0, t; }" : "=r"(a) : "l"(p));
    return a;
}
__device__ __forceinline__ void mma16816(float* d, const uint32_t* a, const uint32_t* b) {
    asm volatile("mma.sync.aligned.m16n8k16.row.col.f32.bf16.bf16.f32 "
                 "{%0,%1,%2,%3}, {%4,%5,%6,%7}, {%8,%9}, {%0,%1,%2,%3};"
                 : "+f"(d[0]), "+f"(d[1]), "+f"(d[2]), "+f"(d[3])
                 : "r"(a[0]), "r"(a[1]), "r"(a[2]), "r"(a[3]), "r"(b[0]), "r"(b[1]));
}
__device__ __forceinline__ void ldsm4(uint32_t* r, uint32_t addr) {
    asm volatile("ldmatrix.sync.aligned.m8n8.x4.shared.b16 {%0,%1,%2,%3}, [%4];"
                 : "=r"(r[0]), "=r"(r[1]), "=r"(r[2]), "=r"(r[3]) : "r"(addr));
}
__device__ __forceinline__ void split2(float v0, float v1, uint32_t& hi, uint32_t& lo) {
    asm("cvt.rn.bf16x2.f32 %0, %1, %2;" : "=r"(hi) : "f"(v1), "f"(v0));
    float f0 = __uint_as_float(hi << 16);
    float f1 = __uint_as_float(hi & 0xFFFF0000u);
    float r0 = v0 - f0, r1 = v1 - f1;
    asm("cvt.rn.bf16x2.f32 %0, %1, %2;" : "=r"(lo) : "f"(r1), "f"(r0));
}

// ---------- Kernel 1: transpose [bp][c][y][x] -> [bp][y][x][c] ----------
__global__ void transpose_planes(const float* __restrict__ in) {
    __shared__ float t[32][33];
    int tx = threadIdx.x, ty = threadIdx.y;
    int xb = blockIdx.x * 32, y = blockIdx.y, bp = blockIdx.z;
    const float* src = in + ((size_t)bp * CDIM) * (RDIM * RDIM) + (size_t)y * RDIM + xb;
#pragma unroll
    for (int i = 0; i < 4; i++) {
        int c = ty + i * 8;
        t[c][tx] = src[(size_t)c * (RDIM * RDIM) + tx];
    }
    __syncthreads();
    float* dst = g_tp + (((size_t)bp * RDIM + y) * RDIM + xb) * CDIM;
#pragma unroll
    for (int i = 0; i < 4; i++) {
        int xl = ty + i * 8;
        dst[(size_t)xl * CDIM + tx] = t[tx][xl];
    }
}

// ---------- Kernel 2: gather + bf16 mma.sync MLP (2 CTAs/SM) ----------
__global__ __launch_bounds__(THREADS, 2)
void fused_triplane_mlp_mma(const float* __restrict__ coords,
                            const float* __restrict__ w0, const float* __restrict__ b0,
                            const float* __restrict__ w1, const float* __restrict__ b1,
                            const float* __restrict__ w2, const float* __restrict__ b2,
                            float* __restrict__ out) {
    extern __shared__ char sm[];
    const uint32_t sb = smem_u32(sm);
    const int tid = threadIdx.x;
    const int wid = tid >> 5;
    const int lane = tid & 31;

    float* sB0 = (float*)(sm + OFF_B0);
    float* sB1 = (float*)(sm + OFF_B1);
    float* sW2 = (float*)(sm + OFF_W2);

    // ---- stage weights: bf16 hi/lo split into padded layouts ----
    for (int i = tid; i < 16384; i += THREADS) {     // w1[g][h], stride 272B
        int g = i >> 7, h = i & 127;
        float v = w1[i];
        __nv_bfloat16 hb = __float2bfloat16(v);
        float res = v - __bfloat162float(hb);
        *(unsigned short*)(sm + OFF_W1HI + g * 272 + h * 2) = *(unsigned short*)&hb;
        __nv_bfloat16 lb = __float2bfloat16(res);
        *(unsigned short*)(sm + OFF_W1LO + g * 272 + h * 2) = *(unsigned short*)&lb;
    }
    for (int i = tid; i < 4096; i += THREADS) {      // w0[j][c], stride 80B
        int j = i >> 5, c = i & 31;
        float v = w0[i];
        __nv_bfloat16 hb = __float2bfloat16(v);
        float res = v - __bfloat162float(hb);
        *(unsigned short*)(sm + OFF_W0HI + j * 80 + c * 2) = *(unsigned short*)&hb;
        __nv_bfloat16 lb = __float2bfloat16(res);
        *(unsigned short*)(sm + OFF_W0LO + j * 80 + c * 2) = *(unsigned short*)&lb;
    }
    if (tid < 128) { sB0[tid] = b0[tid]; sB1[tid] = b1[tid]; sW2[tid] = w2[tid]; }
    const float bias2 = b2[0];
    __syncthreads();

    // ---- lane-fixed ldmatrix base addresses ----
    const int grp = lane >> 3;
    const int idx = lane & 7;
    const uint32_t fA = (uint32_t)((wid * 16 + (lane & 15)) * 80 + (lane >> 4) * 16);
    const uint32_t aHI = sb + OFF_FHI + fA;
    const uint32_t aLO = sb + OFF_FLO + fA;
    const uint32_t b0off = (uint32_t)(((grp >> 1) * 8 + idx) * 80 + (grp & 1) * 16);
    const uint32_t w0HI = sb + OFF_W0HI + b0off;
    const uint32_t w0LO = sb + OFF_W0LO + b0off;
    const uint32_t b1off = (uint32_t)(((grp >> 1) * 8 + idx) * 272 + (grp & 1) * 16);
    const uint32_t w1HI = sb + OFF_W1HI + b1off;
    const uint32_t w1LO = sb + OFF_W1LO + b1off;
    const int pt_sub = lane >> 3;
    const int q = lane & 7;
    char* fhiw = sm + OFF_FHI + (size_t)q * 8;
    char* flow = sm + OFF_FLO + (size_t)q * 8;

    const int c2 = 2 * (lane & 3);

    const int gwarp = blockIdx.x * 8 + wid;
    const int nwarp = gridDim.x * 8;

    for (int wt = gwarp; wt < NWTILES; wt += nwarp) {
        const int pbase = wt * 16;

        // ================= gather: 16 points -> F rows (bf16 hi/lo) =================
        __syncwarp();
#pragma unroll 1
        for (int it = 0; it < 4; it++) {
            const int row = it * 4 + pt_sub;
            const int p = pbase + row;
            const float cx = coords[3 * p + 0];
            const float cy = coords[3 * p + 1];
            const float cz = coords[3 * p + 2];
            const int b = p >> 17;
            float4 acc;
#pragma unroll
            for (int pl = 0; pl < 3; pl++) {
                const float u = (pl == 1) ? cy : cx;
                const float v = (pl == 0) ? cy : cz;
                const float xf = (u + 1.0f) * 127.5f;
                const float yf = (v + 1.0f) * 127.5f;
                const float x0f = floorf(xf), y0f = floorf(yf);
                const float wx = xf - x0f, wy = yf - y0f;
                const int ix0 = (int)x0f, iy0 = (int)y0f;
                const int ix1 = ix0 + 1, iy1 = iy0 + 1;
                const float mx0 = (ix0 >= 0 && ix0 < RDIM) ? 1.0f : 0.0f;
                const float mx1 = (ix1 >= 0 && ix1 < RDIM) ? 1.0f : 0.0f;
                const float my0 = (iy0 >= 0 && iy0 < RDIM) ? 1.0f : 0.0f;
                const float my1 = (iy1 >= 0 && iy1 < RDIM) ? 1.0f : 0.0f;
                const int ix0c = min(max(ix0, 0), RDIM - 1);
                const int ix1c = min(max(ix1, 0), RDIM - 1);
                const int iy0c = min(max(iy0, 0), RDIM - 1);
                const int iy1c = min(max(iy1, 0), RDIM - 1);
                const float w00 = (1.0f - wx) * (1.0f - wy) * mx0 * my0;
                const float w01 = wx * (1.0f - wy) * mx1 * my0;
                const float w10 = (1.0f - wx) * wy * mx0 * my1;
                const float w11 = wx * wy * mx1 * my1;
                const float4* base =
                    (const float4*)(g_tp + ((size_t)(b * 3 + pl) * RDIM * RDIM) * CDIM);
                const float4 a0 = base[(size_t)(iy0c * RDIM + ix0c) * 8 + q];
                const float4 a1 = base[(size_t)(iy0c * RDIM + ix1c) * 8 + q];
                const float4 a2 = base[(size_t)(iy1c * RDIM + ix0c) * 8 + q];
                const float4 a3 = base[(size_t)(iy1c * RDIM + ix1c) * 8 + q];
                float4 s;
                s.x = w00 * a0.x + w01 * a1.x + w10 * a2.x + w11 * a3.x;
                s.y = w00 * a0.y + w01 * a1.y + w10 * a2.y + w11 * a3.y;
                s.z = w00 * a0.z + w01 * a1.z + w10 * a2.z + w11 * a3.z;
                s.w = w00 * a0.w + w01 * a1.w + w10 * a2.w + w11 * a3.w;
                if (pl == 0) acc = s;
                else { acc.x *= s.x; acc.y *= s.y; acc.z *= s.z; acc.w *= s.w; }
            }
            uint2 hi, lo;
            split2(acc.x, acc.y, hi.x, lo.x);
            split2(acc.z, acc.w, hi.y, lo.y);
            const int gr = wid * 16 + row;
            *(uint2*)(fhiw + gr * 80) = hi;
            *(uint2*)(flow + gr * 80) = lo;
        }
        __syncwarp();

        // ================= layer 0: D = F(16x32) x W0^T, in two n-halves ============
        uint32_t A0h[2][4], A0l[2][4];
        ldsm4(A0h[0], aHI);       ldsm4(A0h[1], aHI + 32);
        ldsm4(A0l[0], aLO);       ldsm4(A0l[1], aLO + 32);

        uint32_t A1h[8][4], A1l[8][4];
        float D8[8][4];

#pragma unroll
        for (int nh = 0; nh < 2; nh++) {
#pragma unroll
            for (int m = 0; m < 8; m++) { D8[m][0]=0.f; D8[m][1]=0.f; D8[m][2]=0.f; D8[m][3]=0.f; }
#pragma unroll
            for (int ntp = 0; ntp < 4; ntp++) {
                const uint32_t woff = (uint32_t)((nh * 4 + ntp) * (16 * 80));
#pragma unroll
                for (int kf = 0; kf < 2; kf++) {
                    uint32_t bh[4], bl[4];
                    ldsm4(bh, w0HI + woff + kf * 32);
                    ldsm4(bl, w0LO + woff + kf * 32);
                    mma16816(D8[2 * ntp],     A0h[kf], bh);
                    mma16816(D8[2 * ntp],     A0h[kf], bl);
                    mma16816(D8[2 * ntp],     A0l[kf], bh);
                    mma16816(D8[2 * ntp + 1], A0h[kf], bh + 2);
                    mma16816(D8[2 * ntp + 1], A0h[kf], bl + 2);
                    mma16816(D8[2 * ntp + 1], A0l[kf], bh + 2);
                }
            }
            // epilogue0 (half): relu(D + b0) -> A1 fragments kf = nh*4 + (m>>1)
#pragma unroll
            for (int m = 0; m < 8; m++) {
                const float2 bb = *(const float2*)(sB0 + nh * 64 + 8 * m + c2);
                float v0 = fmaxf(D8[m][0] + bb.x, 0.f);
                float v1 = fmaxf(D8[m][1] + bb.y, 0.f);
                float v2 = fmaxf(D8[m][2] + bb.x, 0.f);
                float v3 = fmaxf(D8[m][3] + bb.y, 0.f);
                const int j = nh * 4 + (m >> 1), h = (m & 1) * 2;
                split2(v0, v1, A1h[j][h],     A1l[j][h]);
                split2(v2, v3, A1h[j][h + 1], A1l[j][h + 1]);
            }
        }

        // ================= layer 1 + layer 2, in two n-halves =================
        float acc0 = 0.f, acc1 = 0.f;
#pragma unroll
        for (int oh = 0; oh < 2; oh++) {
#pragma unroll
            for (int m = 0; m < 8; m++) { D8[m][0]=0.f; D8[m][1]=0.f; D8[m][2]=0.f; D8[m][3]=0.f; }
#pragma unroll
            for (int ntp = 0; ntp < 4; ntp++) {
                const uint32_t woff = (uint32_t)((oh * 4 + ntp) * (16 * 272));
#pragma unroll
                for (int kf = 0; kf < 8; kf++) {
                    uint32_t bh[4], bl[4];
                    ldsm4(bh, w1HI + woff + kf * 32);
                    ldsm4(bl, w1LO + woff + kf * 32);
                    mma16816(D8[2 * ntp],     A1h[kf], bh);
                    mma16816(D8[2 * ntp],     A1h[kf], bl);
                    mma16816(D8[2 * ntp],     A1l[kf], bh);
                    mma16816(D8[2 * ntp + 1], A1h[kf], bh + 2);
                    mma16816(D8[2 * ntp + 1], A1h[kf], bl + 2);
                    mma16816(D8[2 * ntp + 1], A1l[kf], bh + 2);
                }
            }
#pragma unroll
            for (int m = 0; m < 8; m++) {
                const float2 bv = *(const float2*)(sB1 + oh * 64 + 8 * m + c2);
                const float2 wv = *(const float2*)(sW2 + oh * 64 + 8 * m + c2);
                acc0 = fmaf(fmaxf(D8[m][0] + bv.x, 0.f), wv.x, acc0);
                acc0 = fmaf(fmaxf(D8[m][1] + bv.y, 0.f), wv.y, acc0);
                acc1 = fmaf(fmaxf(D8[m][2] + bv.x, 0.f), wv.x, acc1);
                acc1 = fmaf(fmaxf(D8[m][3] + bv.y, 0.f), wv.y, acc1);
            }
        }

        acc0 += __shfl_xor_sync(0xFFFFFFFFu, acc0, 1);
        acc0 += __shfl_xor_sync(0xFFFFFFFFu, acc0, 2);
        acc1 += __shfl_xor_sync(0xFFFFFFFFu, acc1, 1);
        acc1 += __shfl_xor_sync(0xFFFFFFFFu, acc1, 2);
        if ((lane & 3) == 0) {
            const int g = lane >> 2;
            out[pbase + g] = acc0 + bias2;
            out[pbase + g + 8] = acc1 + bias2;
        }
    }
}

// ---------------- host ----------------
extern "C" void kernel_launch(void* const* d_in, const int* in_sizes, int n_in,
                              void* d_out, int out_size) {
    const float* triplanes = (const float*)d_in[0];
    const float* coords    = (const float*)d_in[1];
    const float* w0 = (const float*)d_in[2];
    const float* b0 = (const float*)d_in[3];
    const float* w1 = (const float*)d_in[4];
    const float* b1 = (const float*)d_in[5];
    const float* w2 = (const float*)d_in[6];
    const float* b2 = (const float*)d_in[7];
    float* out = (float*)d_out;

    dim3 tgrid(RDIM / 32, RDIM, 12);
    dim3 tblk(32, 8);
    transpose_planes<<<tgrid, tblk>>>(triplanes);

    static int sms = 0;
    if (sms == 0) {
        cudaDeviceGetAttribute(&sms, cudaDevAttrMultiProcessorCount, 0);
        cudaFuncSetAttribute(fused_triplane_mlp_mma,
                             cudaFuncAttributeMaxDynamicSharedMemorySize, SMEM_BYTES);
    }
    fused_triplane_mlp_mma<<<2 * sms, THREADS, SMEM_BYTES>>>(coords, w0, b0, w1, b1, w2, b2, out);
}